// round 4
// baseline (speedup 1.0000x reference)
#include <cuda_runtime.h>

#define NG   512
#define FDIM 32
#define HH   96
#define WW   96
#define DD   16

// Per-gaussian packed params (3 x float4 each):
//  p0 = {mx, my, mz, opacity}
//  p1 = {a00, a11, a22, a01}   (inv_cov entries pre-scaled by -0.5*log2(e))
//  p2 = {a02, a12, 0, 0}
__device__ float4 g_params[NG * 3];

__device__ __forceinline__ float ex2f(float x) {
    float r;
    asm("ex2.approx.f32 %0, %1;" : "=f"(r) : "f"(x));
    return r;
}

__global__ void prep_kernel(const float* __restrict__ means,
                            const float* __restrict__ scales,
                            const float* __restrict__ rots,
                            const float* __restrict__ opac,
                            const float* __restrict__ cam) {
    int n = threadIdx.x;
    if (n >= NG) return;

    // Camera transform: homo = [m,1] @ C^T ; m' = homo.xyz / homo.w
    float m0 = means[3*n+0], m1 = means[3*n+1], m2 = means[3*n+2];
    float h0 = cam[0]*m0  + cam[1]*m1  + cam[2]*m2  + cam[3];
    float h1 = cam[4]*m0  + cam[5]*m1  + cam[6]*m2  + cam[7];
    float h2 = cam[8]*m0  + cam[9]*m1  + cam[10]*m2 + cam[11];
    float h3 = cam[12]*m0 + cam[13]*m1 + cam[14]*m2 + cam[15];
    float iw = 1.0f / h3;
    float mx = h0*iw, my = h1*iw, mz = h2*iw;

    // Quaternion -> rotation
    float qw = rots[4*n+0], qx = rots[4*n+1], qy = rots[4*n+2], qz = rots[4*n+3];
    float qn = rsqrtf(qw*qw + qx*qx + qy*qy + qz*qz);
    qw *= qn; qx *= qn; qy *= qn; qz *= qn;

    float r00 = 1.f - 2.f*(qy*qy + qz*qz);
    float r01 = 2.f*(qx*qy - qw*qz);
    float r02 = 2.f*(qx*qz + qw*qy);
    float r10 = 2.f*(qx*qy + qw*qz);
    float r11 = 1.f - 2.f*(qx*qx + qz*qz);
    float r12 = 2.f*(qy*qz - qw*qx);
    float r20 = 2.f*(qx*qz - qw*qy);
    float r21 = 2.f*(qy*qz + qw*qx);
    float r22 = 1.f - 2.f*(qx*qx + qy*qy);

    float s0 = scales[3*n+0], s1 = scales[3*n+1], s2 = scales[3*n+2];

    // RS = R * diag(s)  (scale columns), cov = RS RS^T  (double for inversion safety)
    double a0 = (double)(r00*s0), a1 = (double)(r01*s1), a2 = (double)(r02*s2);
    double b0 = (double)(r10*s0), b1 = (double)(r11*s1), b2 = (double)(r12*s2);
    double c0 = (double)(r20*s0), c1 = (double)(r21*s1), c2 = (double)(r22*s2);

    double c00 = a0*a0 + a1*a1 + a2*a2;
    double c01 = a0*b0 + a1*b1 + a2*b2;
    double c02 = a0*c0 + a1*c1 + a2*c2;
    double c11 = b0*b0 + b1*b1 + b2*b2;
    double c12 = b0*c0 + b1*c1 + b2*c2;
    double c22 = c0*c0 + c1*c1 + c2*c2;

    // Symmetric 3x3 inverse via adjugate
    double det = c00*(c11*c22 - c12*c12)
               - c01*(c01*c22 - c02*c12)
               + c02*(c01*c12 - c02*c11);
    double idet = 1.0 / det;
    double i00 = (c11*c22 - c12*c12) * idet;
    double i01 = (c02*c12 - c01*c22) * idet;
    double i02 = (c01*c12 - c02*c11) * idet;
    double i11 = (c00*c22 - c02*c02) * idet;
    double i12 = (c01*c02 - c00*c12) * idet;
    double i22 = (c00*c11 - c01*c01) * idet;

    // Fold -0.5*log2(e) so alpha = op * exp2(q)
    const double S = -0.72134752044448170368;
    float4 p0 = make_float4(mx, my, mz, opac[n]);
    float4 p1 = make_float4((float)(i00*S), (float)(i11*S), (float)(i22*S), (float)(i01*S));
    float4 p2 = make_float4((float)(i02*S), (float)(i12*S), 0.f, 0.f);
    g_params[3*n+0] = p0;
    g_params[3*n+1] = p1;
    g_params[3*n+2] = p2;
}

// Block tile: 4 (d/x) x 8 (w/y) x 8 (h/z) = 256 threads.
// Warp = lanes over d(4) x w(8) at fixed h  -> spatially compact for culling.
__global__ __launch_bounds__(256)
void render_kernel(const float* __restrict__ feats,
                   const float* __restrict__ coord_grid,
                   float* __restrict__ out) {
    __shared__ float4 sp[NG * 3];
    for (int i = threadIdx.x; i < NG * 3; i += 256) sp[i] = g_params[i];
    __syncthreads();

    int t = threadIdx.x;
    int dl = t & 3;
    int wl = (t >> 2) & 7;
    int hl = t >> 5;

    int b  = blockIdx.x;
    int bd = b & 3;          // 4 tiles of 4 in D
    int bw = (b >> 2) % 12;  // 12 tiles of 8 in W
    int bh = b / 48;         // 12 tiles of 8 in H

    int d = bd * 4 + dl;
    int w = bw * 8 + wl;
    int h = bh * 8 + hl;

    int p = (h * WW + w) * DD + d;

    float x = coord_grid[3*p + 0];
    float y = coord_grid[3*p + 1];
    float z = coord_grid[3*p + 2];

    float acc[FDIM];
    #pragma unroll
    for (int j = 0; j < FDIM; j++) acc[j] = 0.f;
    float T = 1.0f;

    for (int g = 0; g < NG; g++) {
        float4 p0 = sp[3*g + 0];
        float4 p1 = sp[3*g + 1];
        float4 p2 = sp[3*g + 2];

        float dx = x - p0.x;
        float dy = y - p0.y;
        float dz = z - p0.z;

        // q = -0.5*log2e * mahalanobis  (scale folded into coefficients)
        float t0 = p1.x*dx + p1.w*dy + p2.x*dz;
        float t1 = p1.w*dx + p1.y*dy + p2.y*dz;
        float t2 = p2.x*dx + p2.y*dy + p1.z*dz;
        float q  = dx*t0 + dy*t1 + dz*t2;

        // Cull: all lanes negligible (alpha < ~3e-7) -> skip features + T update
        if (__all_sync(0xFFFFFFFFu, q < -22.0f)) continue;

        float alpha = p0.w * ex2f(q);
        float wgt   = T * alpha;
        T -= wgt;

        const float4* f4 = reinterpret_cast<const float4*>(feats + g * FDIM);
        #pragma unroll
        for (int j = 0; j < FDIM / 4; j++) {
            float4 fv = __ldg(f4 + j);
            acc[4*j + 0] = fmaf(wgt, fv.x, acc[4*j + 0]);
            acc[4*j + 1] = fmaf(wgt, fv.y, acc[4*j + 1]);
            acc[4*j + 2] = fmaf(wgt, fv.z, acc[4*j + 2]);
            acc[4*j + 3] = fmaf(wgt, fv.w, acc[4*j + 3]);
        }
    }

    float4* o4 = reinterpret_cast<float4*>(out + (size_t)p * FDIM);
    #pragma unroll
    for (int j = 0; j < FDIM / 4; j++) {
        o4[j] = make_float4(acc[4*j+0], acc[4*j+1], acc[4*j+2], acc[4*j+3]);
    }
}

extern "C" void kernel_launch(void* const* d_in, const int* in_sizes, int n_in,
                              void* d_out, int out_size) {
    const float* means  = (const float*)d_in[0];
    const float* scales = (const float*)d_in[1];
    const float* rots   = (const float*)d_in[2];
    const float* opac   = (const float*)d_in[3];
    const float* feats  = (const float*)d_in[4];
    const float* cam    = (const float*)d_in[5];
    const float* cgrid  = (const float*)d_in[6];
    float* out = (float*)d_out;

    prep_kernel<<<1, NG>>>(means, scales, rots, opac, cam);
    render_kernel<<<(HH/8)*(WW/8)*(DD/4), 256>>>(feats, cgrid, out);
}

// round 5
// speedup vs baseline: 1.5611x; 1.5611x over previous
#include <cuda_runtime.h>

#define NG   512
#define FDIM 32
#define HH   96
#define WW   96
#define DD   16
#define CULL_Q  (-18.0f)   // alpha below op*2^-18 ~ 3.8e-6 treated as zero
#define SQRT_CULL 4.2427f  // sqrt(18), slightly rounded up (conservative)

// Per-gaussian packed params (3 x float4 each):
//  p0 = {mx, my, mz, opacity}
//  p1 = {a00, a11, a22, d01}    a = -0.5*log2(e)*inv_cov,  d01 = 2*a01
//  p2 = {d02, d12, u, unused}   d0k = 2*a0k,  u = sqrt(0.72135)/s_min (cull bound)
__device__ float4 g_params[NG * 3];

__device__ __forceinline__ float ex2f(float x) {
    float r;
    asm("ex2.approx.f32 %0, %1;" : "=f"(r) : "f"(x));
    return r;
}

__global__ void prep_kernel(const float* __restrict__ means,
                            const float* __restrict__ scales,
                            const float* __restrict__ rots,
                            const float* __restrict__ opac,
                            const float* __restrict__ cam) {
    int n = threadIdx.x;
    if (n >= NG) return;

    // Camera transform: homo = [m,1] @ C^T ; m' = homo.xyz / homo.w
    float m0 = means[3*n+0], m1 = means[3*n+1], m2 = means[3*n+2];
    float h0 = cam[0]*m0  + cam[1]*m1  + cam[2]*m2  + cam[3];
    float h1 = cam[4]*m0  + cam[5]*m1  + cam[6]*m2  + cam[7];
    float h2 = cam[8]*m0  + cam[9]*m1  + cam[10]*m2 + cam[11];
    float h3 = cam[12]*m0 + cam[13]*m1 + cam[14]*m2 + cam[15];
    float iw = 1.0f / h3;
    float mx = h0*iw, my = h1*iw, mz = h2*iw;

    // Quaternion -> rotation
    float qw = rots[4*n+0], qx = rots[4*n+1], qy = rots[4*n+2], qz = rots[4*n+3];
    float qn = rsqrtf(qw*qw + qx*qx + qy*qy + qz*qz);
    qw *= qn; qx *= qn; qy *= qn; qz *= qn;

    float r00 = 1.f - 2.f*(qy*qy + qz*qz);
    float r01 = 2.f*(qx*qy - qw*qz);
    float r02 = 2.f*(qx*qz + qw*qy);
    float r10 = 2.f*(qx*qy + qw*qz);
    float r11 = 1.f - 2.f*(qx*qx + qz*qz);
    float r12 = 2.f*(qy*qz - qw*qx);
    float r20 = 2.f*(qx*qz - qw*qy);
    float r21 = 2.f*(qy*qz + qw*qx);
    float r22 = 1.f - 2.f*(qx*qx + qy*qy);

    float s0 = scales[3*n+0], s1 = scales[3*n+1], s2 = scales[3*n+2];

    // cov = (R diag(s)) (R diag(s))^T, inverted in double via adjugate
    double a0 = (double)(r00*s0), a1 = (double)(r01*s1), a2 = (double)(r02*s2);
    double b0 = (double)(r10*s0), b1 = (double)(r11*s1), b2 = (double)(r12*s2);
    double c0 = (double)(r20*s0), c1 = (double)(r21*s1), c2 = (double)(r22*s2);

    double c00 = a0*a0 + a1*a1 + a2*a2;
    double c01 = a0*b0 + a1*b1 + a2*b2;
    double c02 = a0*c0 + a1*c1 + a2*c2;
    double c11 = b0*b0 + b1*b1 + b2*b2;
    double c12 = b0*c0 + b1*c1 + b2*c2;
    double c22 = c0*c0 + c1*c1 + c2*c2;

    double det = c00*(c11*c22 - c12*c12)
               - c01*(c01*c22 - c02*c12)
               + c02*(c01*c12 - c02*c11);
    double idet = 1.0 / det;
    double i00 = (c11*c22 - c12*c12) * idet;
    double i01 = (c02*c12 - c01*c22) * idet;
    double i02 = (c01*c12 - c02*c11) * idet;
    double i11 = (c00*c22 - c02*c02) * idet;
    double i12 = (c01*c02 - c00*c12) * idet;
    double i22 = (c00*c11 - c01*c01) * idet;

    // Fold -0.5*log2(e); double the off-diagonals
    const double S = -0.72134752044448170368;
    float smin = fminf(s0, fminf(s1, s2));
    float u = 0.8495f / smin;  // >= sqrt(0.72135)/s_min  (conservative)

    g_params[3*n+0] = make_float4(mx, my, mz, opac[n]);
    g_params[3*n+1] = make_float4((float)(i00*S), (float)(i11*S), (float)(i22*S),
                                  (float)(2.0*i01*S));
    g_params[3*n+2] = make_float4((float)(2.0*i02*S), (float)(2.0*i12*S), u, 0.f);
}

// Block: 256 threads, covers d:4 x w:8 x h:16 cells (2 h-points per thread).
// Warp = d(4) x w(8) lanes at one (h, h+1) pair -> tight footprint for culling.
__global__ __launch_bounds__(256)
void render_kernel(const float* __restrict__ feats,
                   const float* __restrict__ cg,
                   float* __restrict__ out) {
    __shared__ float4 sp[NG * 3];   // compacted params (order preserved)
    __shared__ int    s_idx[NG];
    __shared__ int    s_cnt[17];
    __shared__ float4 s_cb;         // block bounding-sphere {cx,cy,cz,r}

    int t    = threadIdx.x;
    int lane = t & 31;
    int warp = t >> 5;

    int b  = blockIdx.x;
    int bd = b & 3;          // 4 tiles of 4 in D
    int bw = (b >> 2) % 12;  // 12 tiles of 8 in W
    int bh = b / 48;         // 6 tiles of 16 in H
    int d0 = bd * 4, w0 = bw * 8, h0b = bh * 16;

    // Block bounding sphere from the two extreme cell centers
    if (t == 0) {
        int pa = ((h0b     ) * WW + (w0    )) * DD + (d0    );
        int pb = ((h0b + 15) * WW + (w0 + 7)) * DD + (d0 + 3);
        float ax = cg[3*pa], ay = cg[3*pa+1], az = cg[3*pa+2];
        float bx = cg[3*pb], by = cg[3*pb+1], bz = cg[3*pb+2];
        float hx = 0.5f*(bx-ax), hy = 0.5f*(by-ay), hz = 0.5f*(bz-az);
        s_cb = make_float4(0.5f*(ax+bx), 0.5f*(ay+by), 0.5f*(az+bz),
                           sqrtf(hx*hx + hy*hy + hz*hz));
    }
    __syncthreads();
    float4 cb = s_cb;

    // ---- Block-level cull + order-preserving compaction ----
    // keep iff sqrt(m_center) < sqrt(18) + r*u   (A-norm triangle inequality)
    bool k1, k2;
    {
        int g = t;                               // segment = warp
        float4 p0 = __ldg(&g_params[3*g]);
        float4 p1 = __ldg(&g_params[3*g+1]);
        float4 p2 = __ldg(&g_params[3*g+2]);
        float dx = cb.x - p0.x, dy = cb.y - p0.y, dz = cb.z - p0.z;
        float cxy = fmaf(dx, fmaf(p1.x, dx, p1.w*dy), p1.y*dy*dy);
        float l   = fmaf(p2.x, dx, p2.y*dy);
        float m   = -(fmaf(dz, fmaf(p1.z, dz, l), cxy));
        float thr = SQRT_CULL + cb.w * p2.z;
        k1 = m < thr*thr;
    }
    {
        int g = t + 256;                         // segment = 8 + warp
        float4 p0 = __ldg(&g_params[3*g]);
        float4 p1 = __ldg(&g_params[3*g+1]);
        float4 p2 = __ldg(&g_params[3*g+2]);
        float dx = cb.x - p0.x, dy = cb.y - p0.y, dz = cb.z - p0.z;
        float cxy = fmaf(dx, fmaf(p1.x, dx, p1.w*dy), p1.y*dy*dy);
        float l   = fmaf(p2.x, dx, p2.y*dy);
        float m   = -(fmaf(dz, fmaf(p1.z, dz, l), cxy));
        float thr = SQRT_CULL + cb.w * p2.z;
        k2 = m < thr*thr;
    }
    unsigned bal1 = __ballot_sync(0xffffffffu, k1);
    unsigned bal2 = __ballot_sync(0xffffffffu, k2);
    if (lane == 0) { s_cnt[warp] = __popc(bal1); s_cnt[8 + warp] = __popc(bal2); }
    __syncthreads();
    if (t == 0) {
        int acc = 0;
        #pragma unroll
        for (int i = 0; i < 16; i++) { int c = s_cnt[i]; s_cnt[i] = acc; acc += c; }
        s_cnt[16] = acc;
    }
    __syncthreads();
    unsigned lm = (1u << lane) - 1u;
    if (k1) s_idx[s_cnt[warp]     + __popc(bal1 & lm)] = t;
    if (k2) s_idx[s_cnt[8 + warp] + __popc(bal2 & lm)] = t + 256;
    __syncthreads();
    int cnt = s_cnt[16];

    // Stage surviving params into shared, original index tucked into p2.w
    for (int k = t; k < cnt; k += 256) {
        int g = s_idx[k];
        float4 p0 = __ldg(&g_params[3*g]);
        float4 p1 = __ldg(&g_params[3*g+1]);
        float4 p2 = __ldg(&g_params[3*g+2]);
        p2.w = __int_as_float(g);
        sp[3*k] = p0; sp[3*k+1] = p1; sp[3*k+2] = p2;
    }
    __syncthreads();

    // ---- Main loop: 2 points per thread (adjacent h -> share x,y) ----
    int dl = t & 3, wl = (t >> 2) & 7, hl = t >> 5;
    int d = d0 + dl, w = w0 + wl, h = h0b + hl * 2;
    int pA = (h * WW + w) * DD + d;
    int pB = pA + WW * DD;   // h+1

    float x  = cg[3*pA + 0];
    float y  = cg[3*pA + 1];
    float z1 = cg[3*pA + 2];
    float z2 = cg[3*pB + 2];

    float acc1[FDIM], acc2[FDIM];
    #pragma unroll
    for (int j = 0; j < FDIM; j++) { acc1[j] = 0.f; acc2[j] = 0.f; }
    float T1 = 1.0f, T2 = 1.0f;

    const float4* f4 = reinterpret_cast<const float4*>(feats);

    #pragma unroll 1
    for (int k = 0; k < cnt; k++) {
        float4 p0 = sp[3*k];
        float4 p1 = sp[3*k+1];
        float4 p2 = sp[3*k+2];

        float dx  = x  - p0.x;
        float dy  = y  - p0.y;
        float dz1 = z1 - p0.z;
        float dz2 = z2 - p0.z;

        // q = a00 dx^2 + d01 dxdy + a11 dy^2 + (d02 dx + d12 dy) dz + a22 dz^2
        float cxy = fmaf(dx, fmaf(p1.x, dx, p1.w * dy), p1.y * dy * dy);
        float l   = fmaf(p2.x, dx, p2.y * dy);
        float q1  = fmaf(dz1, fmaf(p1.z, dz1, l), cxy);
        float q2  = fmaf(dz2, fmaf(p1.z, dz2, l), cxy);

        if (__all_sync(0xffffffffu, fmaxf(q1, q2) < CULL_Q)) continue;

        float a1 = p0.w * ex2f(q1);
        float a2 = p0.w * ex2f(q2);
        float w1 = T1 * a1; T1 -= w1;
        float w2 = T2 * a2; T2 -= w2;

        int g = __float_as_int(p2.w);
        const float4* fg = f4 + g * (FDIM / 4);
        #pragma unroll
        for (int j = 0; j < FDIM / 4; j++) {
            float4 fv = __ldg(fg + j);
            acc1[4*j+0] = fmaf(w1, fv.x, acc1[4*j+0]);
            acc1[4*j+1] = fmaf(w1, fv.y, acc1[4*j+1]);
            acc1[4*j+2] = fmaf(w1, fv.z, acc1[4*j+2]);
            acc1[4*j+3] = fmaf(w1, fv.w, acc1[4*j+3]);
            acc2[4*j+0] = fmaf(w2, fv.x, acc2[4*j+0]);
            acc2[4*j+1] = fmaf(w2, fv.y, acc2[4*j+1]);
            acc2[4*j+2] = fmaf(w2, fv.z, acc2[4*j+2]);
            acc2[4*j+3] = fmaf(w2, fv.w, acc2[4*j+3]);
        }

        // All transmittances exhausted -> remaining contribution < ~4e-5 abs
        if (__all_sync(0xffffffffu, fmaxf(T1, T2) < 1e-5f)) break;
    }

    float4* oA = reinterpret_cast<float4*>(out + (size_t)pA * FDIM);
    float4* oB = reinterpret_cast<float4*>(out + (size_t)pB * FDIM);
    #pragma unroll
    for (int j = 0; j < FDIM / 4; j++) {
        oA[j] = make_float4(acc1[4*j+0], acc1[4*j+1], acc1[4*j+2], acc1[4*j+3]);
        oB[j] = make_float4(acc2[4*j+0], acc2[4*j+1], acc2[4*j+2], acc2[4*j+3]);
    }
}

extern "C" void kernel_launch(void* const* d_in, const int* in_sizes, int n_in,
                              void* d_out, int out_size) {
    const float* means  = (const float*)d_in[0];
    const float* scales = (const float*)d_in[1];
    const float* rots   = (const float*)d_in[2];
    const float* opac   = (const float*)d_in[3];
    const float* feats  = (const float*)d_in[4];
    const float* cam    = (const float*)d_in[5];
    const float* cgrid  = (const float*)d_in[6];
    float* out = (float*)d_out;

    prep_kernel<<<1, NG>>>(means, scales, rots, opac, cam);
    render_kernel<<<(DD/4) * (WW/8) * (HH/16), 256>>>(feats, cgrid, out);
}

// round 6
// speedup vs baseline: 1.6461x; 1.0544x over previous
#include <cuda_runtime.h>

#define NG   512
#define FDIM 32
#define HH   96
#define WW   96
#define DD   16
#define CULL_Q  (-18.0f)   // alpha below op*2^-18 ~ 3.8e-6 treated as zero
#define SQRT_CULL 4.2427f  // sqrt(18), slightly rounded up (conservative)

// Per-gaussian packed params (3 x float4 each):
//  p0 = {mx, my, mz, opacity}
//  p1 = {a00, a11, a22, d01}    a = -0.5*log2(e)*inv_cov,  d01 = 2*a01
//  p2 = {d02, d12, u, unused}   d0k = 2*a0k,  u = sqrt(0.72135)/s_min (cull bound)
__device__ float4 g_params[NG * 3];

__device__ __forceinline__ float ex2f(float x) {
    float r;
    asm("ex2.approx.f32 %0, %1;" : "=f"(r) : "f"(x));
    return r;
}

__global__ void prep_kernel(const float* __restrict__ means,
                            const float* __restrict__ scales,
                            const float* __restrict__ rots,
                            const float* __restrict__ opac,
                            const float* __restrict__ cam) {
    int n = threadIdx.x;
    if (n >= NG) return;

    float m0 = means[3*n+0], m1 = means[3*n+1], m2 = means[3*n+2];
    float h0 = cam[0]*m0  + cam[1]*m1  + cam[2]*m2  + cam[3];
    float h1 = cam[4]*m0  + cam[5]*m1  + cam[6]*m2  + cam[7];
    float h2 = cam[8]*m0  + cam[9]*m1  + cam[10]*m2 + cam[11];
    float h3 = cam[12]*m0 + cam[13]*m1 + cam[14]*m2 + cam[15];
    float iw = 1.0f / h3;
    float mx = h0*iw, my = h1*iw, mz = h2*iw;

    float qw = rots[4*n+0], qx = rots[4*n+1], qy = rots[4*n+2], qz = rots[4*n+3];
    float qn = rsqrtf(qw*qw + qx*qx + qy*qy + qz*qz);
    qw *= qn; qx *= qn; qy *= qn; qz *= qn;

    float r00 = 1.f - 2.f*(qy*qy + qz*qz);
    float r01 = 2.f*(qx*qy - qw*qz);
    float r02 = 2.f*(qx*qz + qw*qy);
    float r10 = 2.f*(qx*qy + qw*qz);
    float r11 = 1.f - 2.f*(qx*qx + qz*qz);
    float r12 = 2.f*(qy*qz - qw*qx);
    float r20 = 2.f*(qx*qz - qw*qy);
    float r21 = 2.f*(qy*qz + qw*qx);
    float r22 = 1.f - 2.f*(qx*qx + qy*qy);

    float s0 = scales[3*n+0], s1 = scales[3*n+1], s2 = scales[3*n+2];

    double a0 = (double)(r00*s0), a1 = (double)(r01*s1), a2 = (double)(r02*s2);
    double b0 = (double)(r10*s0), b1 = (double)(r11*s1), b2 = (double)(r12*s2);
    double c0 = (double)(r20*s0), c1 = (double)(r21*s1), c2 = (double)(r22*s2);

    double c00 = a0*a0 + a1*a1 + a2*a2;
    double c01 = a0*b0 + a1*b1 + a2*b2;
    double c02 = a0*c0 + a1*c1 + a2*c2;
    double c11 = b0*b0 + b1*b1 + b2*b2;
    double c12 = b0*c0 + b1*c1 + b2*c2;
    double c22 = c0*c0 + c1*c1 + c2*c2;

    double det = c00*(c11*c22 - c12*c12)
               - c01*(c01*c22 - c02*c12)
               + c02*(c01*c12 - c02*c11);
    double idet = 1.0 / det;
    double i00 = (c11*c22 - c12*c12) * idet;
    double i01 = (c02*c12 - c01*c22) * idet;
    double i02 = (c01*c12 - c02*c11) * idet;
    double i11 = (c00*c22 - c02*c02) * idet;
    double i12 = (c01*c02 - c00*c12) * idet;
    double i22 = (c00*c11 - c01*c01) * idet;

    const double S = -0.72134752044448170368;
    float smin = fminf(s0, fminf(s1, s2));
    float u = 0.8495f / smin;  // >= sqrt(0.72135)/s_min (conservative)

    g_params[3*n+0] = make_float4(mx, my, mz, opac[n]);
    g_params[3*n+1] = make_float4((float)(i00*S), (float)(i11*S), (float)(i22*S),
                                  (float)(2.0*i01*S));
    g_params[3*n+2] = make_float4((float)(2.0*i02*S), (float)(2.0*i12*S), u, 0.f);
}

// Block: 128 threads, covers d:4 x w:8 x h:8 cells (2 h-points per thread).
// Warp = d(4) x w(8) lanes at one (h, h+1) pair -> tight footprint for culling.
__global__ __launch_bounds__(128, 5)
void render_kernel(const float* __restrict__ feats,
                   const float* __restrict__ cg,
                   float* __restrict__ out) {
    __shared__ float4 sp[NG * 3];   // compacted params (order preserved)
    __shared__ int    s_idx[NG];
    __shared__ int    s_cnt[17];
    __shared__ float4 s_cb;         // block bounding-sphere {cx,cy,cz,r}

    int t    = threadIdx.x;
    int lane = t & 31;
    int warp = t >> 5;              // 0..3

    int b  = blockIdx.x;
    int bd = b & 3;          // 4 tiles of 4 in D
    int bw = (b >> 2) % 12;  // 12 tiles of 8 in W
    int bh = b / 48;         // 12 tiles of 8 in H
    int d0 = bd * 4, w0 = bw * 8, h0b = bh * 8;

    // Block bounding sphere from the two extreme cell centers
    if (t == 0) {
        int pa = ((h0b    ) * WW + (w0    )) * DD + (d0    );
        int pb = ((h0b + 7) * WW + (w0 + 7)) * DD + (d0 + 3);
        float ax = cg[3*pa], ay = cg[3*pa+1], az = cg[3*pa+2];
        float bx = cg[3*pb], by = cg[3*pb+1], bz = cg[3*pb+2];
        float hx = 0.5f*(bx-ax), hy = 0.5f*(by-ay), hz = 0.5f*(bz-az);
        s_cb = make_float4(0.5f*(ax+bx), 0.5f*(ay+by), 0.5f*(az+bz),
                           sqrtf(hx*hx + hy*hy + hz*hz));
    }
    __syncthreads();
    float4 cb = s_cb;

    // ---- Block-level cull + order-preserving compaction ----
    // 4 gaussians per thread; segment s = c*4 + warp covers g = s*32 + lane
    // (segments in increasing s <-> increasing g: order preserved).
    bool keep[4];
    unsigned bal[4];
    #pragma unroll
    for (int c = 0; c < 4; c++) {
        int g = c * 128 + t;
        float4 p0 = __ldg(&g_params[3*g]);
        float4 p1 = __ldg(&g_params[3*g+1]);
        float4 p2 = __ldg(&g_params[3*g+2]);
        float dx = cb.x - p0.x, dy = cb.y - p0.y, dz = cb.z - p0.z;
        float cxy = fmaf(dx, fmaf(p1.x, dx, p1.w*dy), p1.y*dy*dy);
        float l   = fmaf(p2.x, dx, p2.y*dy);
        float m   = -(fmaf(dz, fmaf(p1.z, dz, l), cxy));  // +0.72*mahal(center)
        float thr = SQRT_CULL + cb.w * p2.z;
        keep[c] = m < thr*thr;
        bal[c]  = __ballot_sync(0xffffffffu, keep[c]);
        if (lane == 0) s_cnt[c*4 + warp] = __popc(bal[c]);
    }
    __syncthreads();
    if (t == 0) {
        int acc = 0;
        #pragma unroll
        for (int i = 0; i < 16; i++) { int c = s_cnt[i]; s_cnt[i] = acc; acc += c; }
        s_cnt[16] = acc;
    }
    __syncthreads();
    unsigned lm = (1u << lane) - 1u;
    #pragma unroll
    for (int c = 0; c < 4; c++) {
        if (keep[c]) s_idx[s_cnt[c*4 + warp] + __popc(bal[c] & lm)] = c * 128 + t;
    }
    __syncthreads();
    int cnt = s_cnt[16];

    // Stage surviving params into shared, original index tucked into p2.w
    for (int k = t; k < cnt; k += 128) {
        int g = s_idx[k];
        float4 p0 = __ldg(&g_params[3*g]);
        float4 p1 = __ldg(&g_params[3*g+1]);
        float4 p2 = __ldg(&g_params[3*g+2]);
        p2.w = __int_as_float(g);
        sp[3*k] = p0; sp[3*k+1] = p1; sp[3*k+2] = p2;
    }
    __syncthreads();

    // ---- Main loop: 2 points per thread (adjacent h -> share x,y) ----
    int dl = t & 3, wl = (t >> 2) & 7, hp = t >> 5;
    int d = d0 + dl, w = w0 + wl, h = h0b + hp * 2;
    int pA = (h * WW + w) * DD + d;
    int pB = pA + WW * DD;   // h+1

    float x  = cg[3*pA + 0];
    float y  = cg[3*pA + 1];
    float z1 = cg[3*pA + 2];
    float z2 = cg[3*pB + 2];

    float acc1[FDIM], acc2[FDIM];
    #pragma unroll
    for (int j = 0; j < FDIM; j++) { acc1[j] = 0.f; acc2[j] = 0.f; }
    float T1 = 1.0f, T2 = 1.0f;

    const float4* f4 = reinterpret_cast<const float4*>(feats);

    #pragma unroll 1
    for (int k = 0; k < cnt; k++) {
        float4 p0 = sp[3*k];
        float4 p1 = sp[3*k+1];
        float4 p2 = sp[3*k+2];

        float dx  = x  - p0.x;
        float dy  = y  - p0.y;
        float dz1 = z1 - p0.z;
        float dz2 = z2 - p0.z;

        // q = a00 dx^2 + d01 dxdy + a11 dy^2 + (d02 dx + d12 dy) dz + a22 dz^2
        float cxy = fmaf(dx, fmaf(p1.x, dx, p1.w * dy), p1.y * dy * dy);
        float l   = fmaf(p2.x, dx, p2.y * dy);
        float q1  = fmaf(dz1, fmaf(p1.z, dz1, l), cxy);
        float q2  = fmaf(dz2, fmaf(p1.z, dz2, l), cxy);

        if (__all_sync(0xffffffffu, fmaxf(q1, q2) < CULL_Q)) continue;

        float a1 = p0.w * ex2f(q1);
        float a2 = p0.w * ex2f(q2);
        float w1 = T1 * a1; T1 -= w1;
        float w2 = T2 * a2; T2 -= w2;

        int g = __float_as_int(p2.w);
        const float4* fg = f4 + g * (FDIM / 4);
        #pragma unroll
        for (int j = 0; j < FDIM / 4; j++) {
            float4 fv = __ldg(fg + j);
            acc1[4*j+0] = fmaf(w1, fv.x, acc1[4*j+0]);
            acc1[4*j+1] = fmaf(w1, fv.y, acc1[4*j+1]);
            acc1[4*j+2] = fmaf(w1, fv.z, acc1[4*j+2]);
            acc1[4*j+3] = fmaf(w1, fv.w, acc1[4*j+3]);
            acc2[4*j+0] = fmaf(w2, fv.x, acc2[4*j+0]);
            acc2[4*j+1] = fmaf(w2, fv.y, acc2[4*j+1]);
            acc2[4*j+2] = fmaf(w2, fv.z, acc2[4*j+2]);
            acc2[4*j+3] = fmaf(w2, fv.w, acc2[4*j+3]);
        }

        // All transmittances exhausted -> remaining contribution < ~4e-5 abs
        if (__all_sync(0xffffffffu, fmaxf(T1, T2) < 1e-5f)) break;
    }

    float4* oA = reinterpret_cast<float4*>(out + (size_t)pA * FDIM);
    float4* oB = reinterpret_cast<float4*>(out + (size_t)pB * FDIM);
    #pragma unroll
    for (int j = 0; j < FDIM / 4; j++) {
        oA[j] = make_float4(acc1[4*j+0], acc1[4*j+1], acc1[4*j+2], acc1[4*j+3]);
        oB[j] = make_float4(acc2[4*j+0], acc2[4*j+1], acc2[4*j+2], acc2[4*j+3]);
    }
}

extern "C" void kernel_launch(void* const* d_in, const int* in_sizes, int n_in,
                              void* d_out, int out_size) {
    const float* means  = (const float*)d_in[0];
    const float* scales = (const float*)d_in[1];
    const float* rots   = (const float*)d_in[2];
    const float* opac   = (const float*)d_in[3];
    const float* feats  = (const float*)d_in[4];
    const float* cam    = (const float*)d_in[5];
    const float* cgrid  = (const float*)d_in[6];
    float* out = (float*)d_out;

    prep_kernel<<<1, NG>>>(means, scales, rots, opac, cam);
    render_kernel<<<(DD/4) * (WW/8) * (HH/8), 128>>>(feats, cgrid, out);
}